// round 13
// baseline (speedup 1.0000x reference)
#include <cuda_runtime.h>
#include <cuda_fp16.h>
#include <cstdint>

#define VOCAB 32000
#define HID   768
#define HS1   128
#define MT    256                 // CTA M tile
#define KT    32
#define NKT   (HID / KT)          // 24 K-tiles

#define SA    80                  // A row stride: 32 fp16 (64B) + 16B pad
#define SB    80                  // B row stride: 64B h-only + 16B pad
#define OFF_B 20480               // 256*SA
#define STAGE_BYTES 30720         // OFF_B + 128*SB
#define SG       132              // epilogue gather row stride (f32)
#define OFF_RED  135168           // 256*132*4
#define SMEM_BYTES 144384         // OFF_RED + 256*9*4

__device__ int g_tk_is64;
// packed fp16 weights per (tile t, n): 64B = k0..31 as half2 pairs
__device__ uint4 g_Bpk[(size_t)NKT * HS1 * 4];

__device__ __forceinline__ uint32_t smem_u32(const void* p) {
    uint32_t a;
    asm("{ .reg .u64 t; cvta.to.shared.u64 t, %1; cvt.u32.u64 %0, t; }" : "=r"(a) : "l"(p));
    return a;
}
__device__ __forceinline__ void cp16(uint32_t dst, const void* src) {
    asm volatile("cp.async.ca.shared.global [%0], [%1], 16;" :: "r"(dst), "l"(src));
}
#define CP_COMMIT() asm volatile("cp.async.commit_group;" ::: "memory")
#define CP_WAIT1()  asm volatile("cp.async.wait_group 1;" ::: "memory")

#define LM4(r, addr)                                                            \
    asm volatile("ldmatrix.sync.aligned.m8n8.x4.shared.b16 {%0,%1,%2,%3}, [%4];"\
        : "=r"((r)[0]), "=r"((r)[1]), "=r"((r)[2]), "=r"((r)[3]) : "r"(addr))

#define MMA_F16(d, a, b0, b1)                                                   \
    asm volatile("mma.sync.aligned.m16n8k16.row.col.f32.f16.f16.f32 "           \
        "{%0,%1,%2,%3}, {%4,%5,%6,%7}, {%8,%9}, {%0,%1,%2,%3};"                 \
        : "+f"((d)[0]), "+f"((d)[1]), "+f"((d)[2]), "+f"((d)[3])                \
        : "r"((a)[0]), "r"((a)[1]), "r"((a)[2]), "r"((a)[3]), "r"(b0), "r"(b1))

// ---- prep: coalesced transpose + fp16 convert; tk-dtype probe folded in ----
__global__ void prep_w_kernel(const float* __restrict__ W1,
                              const unsigned int* __restrict__ tkw) {
    __shared__ float sm[KT][HS1 + 4];
    const int t = blockIdx.x, tid = threadIdx.x;
    if (t == 0 && tid < 32) {   // tk dtype probe: int64 -> all odd words zero
        unsigned int v = (tid >= 1) ? tkw[2 * tid - 1] : 0u;
        unsigned int any = __ballot_sync(0xffffffffu, v != 0u);
        if (tid == 0) g_tk_is64 = (any == 0u) ? 1 : 0;
    }
#pragma unroll
    for (int i = 0; i < 16; i++) {            // coalesced read 32k x 128n
        int u = i * 256 + tid;
        int k = u >> 7, n = u & 127;
        sm[k][n] = W1[(size_t)(VOCAB + t * KT + k) * HS1 + n];
    }
    __syncthreads();
#pragma unroll
    for (int i = 0; i < 2; i++) {             // emit [n][64B: k-major half2]
        int u = i * 256 + tid;
        int n = u >> 2, c = u & 3;
        int k0 = c * 8;
        uint4 o;
#pragma unroll
        for (int q = 0; q < 4; q++) {
            __half2 h = __floats2half2_rn(sm[k0 + 2 * q][n], sm[k0 + 2 * q + 1][n]);
            ((uint32_t*)&o)[q] = *(uint32_t*)&h;
        }
        g_Bpk[((size_t)t * HS1 + n) * 4 + c] = o;
    }
}

// ---------------- main fused kernel ----------------
__global__ __launch_bounds__(256, 1)
void cls_mma_kernel(const int*   __restrict__ tkw,
                    const float* __restrict__ hs0,
                    const float* __restrict__ W1,
                    const float* __restrict__ b1,
                    const float* __restrict__ W2,
                    const float* __restrict__ b2,
                    float*       __restrict__ out)
{
    extern __shared__ char smem[];
    const uint32_t sb = smem_u32(smem);
    const int tid = threadIdx.x;
    const int lane = tid & 31, wid = tid >> 5;
    const int wm = wid & 3;            // warp row (4) -> 64 M-rows
    const int wn = wid >> 2;           // warp col (2) -> 64 N-cols
    const int g  = lane >> 2;          // 0..7
    const int q4 = lane & 3;           // 0..3
    const int m0 = blockIdx.x * MT;

    // ldmatrix per-thread source addresses
    const int aRow = (lane & 7) + ((lane >> 3) & 1) * 8;
    const int aK   = (lane >> 4) * 8;
    const uint32_t aBase = (uint32_t)((wm * 64 + aRow) * SA + aK * 2);
    // B: matrices {b0(j0), b1(j0), b0(j1), b1(j1)}; lanes16-31 -> j1 (+8 n rows)
    const uint32_t bBase = (uint32_t)(OFF_B
        + (wn * 64 + (lane & 7) + ((lane >> 4) & 1) * 8) * SB
        + ((lane >> 3) & 1) * 16);

    float acc[4][8][4];
#pragma unroll
    for (int mt = 0; mt < 4; mt++)
#pragma unroll
        for (int j = 0; j < 8; j++)
#pragma unroll
            for (int e = 0; e < 4; e++) acc[mt][j][e] = 0.f;

    const int r_ld = tid >> 3, c_ld = tid & 7;
    uint2 aH[8];                       // A(t) staging, pre-converted fp16
    auto ldgA = [&](int t) {
#pragma unroll
        for (int i = 0; i < 8; i++) {
            float4 v = *(const float4*)(hs0 + (size_t)(m0 + r_ld + i * 32) * HID
                                        + t * KT + c_ld * 4);
            __half2 h0 = __floats2half2_rn(v.x, v.y);
            __half2 h1 = __floats2half2_rn(v.z, v.w);
            aH[i] = make_uint2(*(uint32_t*)&h0, *(uint32_t*)&h1);
        }
    };
    auto stsA = [&](int s) {
        uint32_t base = sb + s * STAGE_BYTES;
#pragma unroll
        for (int i = 0; i < 8; i++)
            asm volatile("st.shared.v2.b32 [%0], {%1,%2};"
                :: "r"(base + (r_ld + i * 32) * SA + c_ld * 8),
                   "r"(aH[i].x), "r"(aH[i].y));
    };
    auto cpB = [&](int s, int t) {
        uint32_t base = sb + s * STAGE_BYTES + OFF_B;
        const uint4* src = g_Bpk + (size_t)t * HS1 * 4;
#pragma unroll
        for (int i = 0; i < 2; i++) {
            int q = i * 256 + tid, n = q >> 2, c = q & 3;
            cp16(base + n * SB + c * 16, src + n * 4 + c);
        }
        CP_COMMIT();
    };

    auto compute = [&](int s) {
        uint32_t base = sb + s * STAGE_BYTES;
#pragma unroll
        for (int ks = 0; ks < 2; ks++) {
            uint32_t a[4][4];
#pragma unroll
            for (int mt = 0; mt < 4; mt++)
                LM4(a[mt], base + aBase + mt * 16 * SA + ks * 32);
#pragma unroll
            for (int p = 0; p < 4; p++) {                     // j-pairs
                uint32_t b[4];                                // {b0,b1}(j0) {b0,b1}(j1)
                LM4(b, base + bBase + p * 16 * SB + ks * 32);
#pragma unroll
                for (int mt = 0; mt < 4; mt++) {
                    MMA_F16(acc[mt][2 * p],     a[mt], b[0], b[1]);
                    MMA_F16(acc[mt][2 * p + 1], a[mt], b[2], b[3]);
                }
            }
        }
    };

    // ---- pipelined mainloop ----
    cpB(0, 0); cpB(1, 1);
    ldgA(0); stsA(0); ldgA(1);
    for (int t = 0; t < NKT; t++) {
        CP_WAIT1();                       // B(t) arrived
        __syncthreads();                  // A(t)/B(t) visible
        if (t + 1 < NKT) { stsA((t + 1) & 1); if (t + 2 < NKT) ldgA(t + 2); }
        compute(t & 1);
        __syncthreads();                  // stage t&1 free
        if (t + 2 < NKT) cpB(t & 1, t + 2); else CP_COMMIT();
    }

    // ---- epilogue: gather + bias + relu + dot(W2) + reduce ----
    const int is64 = g_tk_is64;
    {   // stage gather matrix G[256][128] f32 into (reused) SMEM
        int m = m0 + tid;
        int tok = tkw[is64 ? 2 * m : m];
        const float4* src = (const float4*)(W1 + (size_t)tok * HS1);
        float4* dst = (float4*)((float*)smem + tid * SG);
#pragma unroll
        for (int i = 0; i < 32; i++) dst[i] = src[i];
    }
    float b1v[16], w2v[16];
#pragma unroll
    for (int j = 0; j < 8; j++) {
        int col = wn * 64 + j * 8 + 2 * q4;
        b1v[j * 2] = b1[col];  b1v[j * 2 + 1] = b1[col + 1];
        w2v[j * 2] = W2[col];  w2v[j * 2 + 1] = W2[col + 1];
    }
    __syncthreads();

    float* red = (float*)(smem + OFF_RED);
    const float* G = (const float*)smem;
#pragma unroll
    for (int mt = 0; mt < 4; mt++)
#pragma unroll
        for (int h = 0; h < 2; h++) {
            int row = wm * 64 + mt * 16 + h * 8 + g;
            const float* Gr = G + row * SG + wn * 64;
            float p = 0.f;
#pragma unroll
            for (int j = 0; j < 8; j++) {
                float x0 = acc[mt][j][h * 2 + 0] + Gr[j * 8 + 2 * q4]     + b1v[j * 2];
                float x1 = acc[mt][j][h * 2 + 1] + Gr[j * 8 + 2 * q4 + 1] + b1v[j * 2 + 1];
                p = fmaf(fmaxf(x0, 0.f), w2v[j * 2],     p);
                p = fmaf(fmaxf(x1, 0.f), w2v[j * 2 + 1], p);
            }
            red[row * 9 + wn * 4 + q4] = p;
        }
    __syncthreads();

    {
        float s = 0.f;
#pragma unroll
        for (int x = 0; x < 8; x++) s += red[tid * 9 + x];
        out[m0 + tid] = s + b2[0];
    }
}

extern "C" void kernel_launch(void* const* d_in, const int* in_sizes, int n_in,
                              void* d_out, int out_size)
{
    const int*   tkw = (const int*)d_in[0];
    const float* hs0 = (const float*)d_in[1];
    const float* W1  = (const float*)d_in[2];
    const float* b1  = (const float*)d_in[3];
    const float* W2  = (const float*)d_in[4];
    const float* b2  = (const float*)d_in[5];
    float* out = (float*)d_out;

    const int M = in_sizes[1] / HID;   // tokens from hs0 (tk-dtype agnostic)

    cudaFuncSetAttribute(cls_mma_kernel,
                         cudaFuncAttributeMaxDynamicSharedMemorySize, SMEM_BYTES);

    prep_w_kernel<<<NKT, 256>>>(W1, (const unsigned int*)tkw);
    cls_mma_kernel<<<M / MT, 256, SMEM_BYTES>>>(tkw, hs0, W1, b1, W2, b2, out);
}

// round 14
// speedup vs baseline: 1.1464x; 1.1464x over previous
#include <cuda_runtime.h>
#include <cuda_fp16.h>
#include <cstdint>

#define VOCAB 32000
#define HID   768
#define HS1   128
#define MT    128
#define KT    32
#define NKT   (HID / KT)          // 24 K-tiles

#define SA    80                  // A row stride: 32 fp16 (64B) + 16B pad
#define SB    80                  // B row stride: 64B h-only + 16B pad
#define OFF_B 10240               // 128*SA
#define STAGE_BYTES 20480         // OFF_B + 128*SB
#define NSTAGE 4
#define SMEM_BYTES  81920         // 4 stages; epilogue (72192B) reuses this
#define SG       132              // epilogue gather row stride (f32)
#define OFF_RED  67584            // 128*132*4

__device__ int g_tk_is64;
// packed fp16 weights per (tile t, n): 64B = k0..31 as half2 pairs
__device__ uint4 g_Bpk[(size_t)NKT * HS1 * 4];

__device__ __forceinline__ uint32_t smem_u32(const void* p) {
    uint32_t a;
    asm("{ .reg .u64 t; cvta.to.shared.u64 t, %1; cvt.u32.u64 %0, t; }" : "=r"(a) : "l"(p));
    return a;
}
__device__ __forceinline__ void cp16cg(uint32_t dst, const void* src) {
    asm volatile("cp.async.cg.shared.global [%0], [%1], 16;" :: "r"(dst), "l"(src));
}
#define CP_COMMIT() asm volatile("cp.async.commit_group;" ::: "memory")
#define CP_WAIT2()  asm volatile("cp.async.wait_group 2;" ::: "memory")

#define LM4(r, addr)                                                            \
    asm volatile("ldmatrix.sync.aligned.m8n8.x4.shared.b16 {%0,%1,%2,%3}, [%4];"\
        : "=r"((r)[0]), "=r"((r)[1]), "=r"((r)[2]), "=r"((r)[3]) : "r"(addr))

#define MMA_F16(d, a, b0, b1)                                                   \
    asm volatile("mma.sync.aligned.m16n8k16.row.col.f32.f16.f16.f32 "           \
        "{%0,%1,%2,%3}, {%4,%5,%6,%7}, {%8,%9}, {%0,%1,%2,%3};"                 \
        : "+f"((d)[0]), "+f"((d)[1]), "+f"((d)[2]), "+f"((d)[3])                \
        : "r"((a)[0]), "r"((a)[1]), "r"((a)[2]), "r"((a)[3]), "r"(b0), "r"(b1))

// ---- prep: coalesced transpose + fp16 convert; tk-dtype probe folded in ----
__global__ void prep_w_kernel(const float* __restrict__ W1,
                              const unsigned int* __restrict__ tkw) {
    __shared__ float sm[KT][HS1 + 4];
    const int t = blockIdx.x, tid = threadIdx.x;
    if (t == 0 && tid < 32) {   // tk dtype probe: int64 -> all odd words zero
        unsigned int v = (tid >= 1) ? tkw[2 * tid - 1] : 0u;
        unsigned int any = __ballot_sync(0xffffffffu, v != 0u);
        if (tid == 0) g_tk_is64 = (any == 0u) ? 1 : 0;
    }
#pragma unroll
    for (int i = 0; i < 16; i++) {            // coalesced read 32k x 128n
        int u = i * 256 + tid;
        int k = u >> 7, n = u & 127;
        sm[k][n] = W1[(size_t)(VOCAB + t * KT + k) * HS1 + n];
    }
    __syncthreads();
#pragma unroll
    for (int i = 0; i < 2; i++) {             // emit [n][64B: k-major half2]
        int u = i * 256 + tid;
        int n = u >> 2, c = u & 3;
        int k0 = c * 8;
        uint4 o;
#pragma unroll
        for (int q = 0; q < 4; q++) {
            __half2 h = __floats2half2_rn(sm[k0 + 2 * q][n], sm[k0 + 2 * q + 1][n]);
            ((uint32_t*)&o)[q] = *(uint32_t*)&h;
        }
        g_Bpk[((size_t)t * HS1 + n) * 4 + c] = o;
    }
}

// ---------------- main fused kernel ----------------
__global__ __launch_bounds__(256, 2)
void cls_mma_kernel(const int*   __restrict__ tkw,
                    const float* __restrict__ hs0,
                    const float* __restrict__ W1,
                    const float* __restrict__ b1,
                    const float* __restrict__ W2,
                    const float* __restrict__ b2,
                    float*       __restrict__ out)
{
    extern __shared__ char smem[];
    const uint32_t sb = smem_u32(smem);
    const int tid = threadIdx.x;
    const int lane = tid & 31, wid = tid >> 5;
    const int wm = wid & 3;            // warp row (4) -> 32 M-rows
    const int wn = wid >> 2;           // warp col (2) -> 64 N-cols
    const int g  = lane >> 2;          // 0..7
    const int q4 = lane & 3;           // 0..3
    const int m0 = blockIdx.x * MT;

    // hoist epilogue gather index (dependency started early)
    const int tok_ep = tkw[g_tk_is64 ? 2 * (m0 + (tid >> 1)) : (m0 + (tid >> 1))];

    // ldmatrix per-thread source addresses
    const int aRow = (lane & 7) + ((lane >> 3) & 1) * 8;
    const int aK   = (lane >> 4) * 8;
    const uint32_t aBase = (uint32_t)((wm * 32 + aRow) * SA + aK * 2);
    // B: matrices {b0(j0), b1(j0), b0(j1), b1(j1)}; lanes16-31 -> j1 (+8 n rows)
    const uint32_t bBase = (uint32_t)(OFF_B
        + (wn * 64 + (lane & 7) + ((lane >> 4) & 1) * 8) * SB
        + ((lane >> 3) & 1) * 16);

    float acc[2][8][4];
#pragma unroll
    for (int mt = 0; mt < 2; mt++)
#pragma unroll
        for (int j = 0; j < 8; j++)
#pragma unroll
            for (int e = 0; e < 4; e++) acc[mt][j][e] = 0.f;

    const int r_ld = tid >> 3, c_ld = tid & 7;
    uint2 aH[4];                                              // A staging, fp16
    auto ldgA = [&](int t) {
#pragma unroll
        for (int i = 0; i < 4; i++) {
            float4 v = *(const float4*)(hs0 + (size_t)(m0 + r_ld + i * 32) * HID
                                        + t * KT + c_ld * 4);
            __half2 h0 = __floats2half2_rn(v.x, v.y);
            __half2 h1 = __floats2half2_rn(v.z, v.w);
            aH[i] = make_uint2(*(uint32_t*)&h0, *(uint32_t*)&h1);
        }
    };
    auto stsA = [&](int s) {
        uint32_t base = sb + s * STAGE_BYTES;
#pragma unroll
        for (int i = 0; i < 4; i++)
            asm volatile("st.shared.v2.b32 [%0], {%1,%2};"
                :: "r"(base + (r_ld + i * 32) * SA + c_ld * 8),
                   "r"(aH[i].x), "r"(aH[i].y));
    };
    auto cpB = [&](int s, int t) {                            // one commit per call
        uint32_t base = sb + s * STAGE_BYTES + OFF_B;
        const uint4* src = g_Bpk + (size_t)t * HS1 * 4;
#pragma unroll
        for (int i = 0; i < 2; i++) {
            int q = i * 256 + tid, n = q >> 2, c = q & 3;
            cp16cg(base + n * SB + c * 16, src + n * 4 + c);
        }
        CP_COMMIT();
    };

    auto compute = [&](int s) {
        uint32_t base = sb + s * STAGE_BYTES;
#pragma unroll
        for (int ks = 0; ks < 2; ks++) {
            uint32_t a0[4], a1[4];
            LM4(a0, base + aBase + ks * 32);                  // mt=0 m16k16 frag
            LM4(a1, base + aBase + 16 * SA + ks * 32);        // mt=1
#pragma unroll
            for (int p = 0; p < 4; p++) {                     // j-pairs
                uint32_t b[4];                                // {b0,b1}(j0) {b0,b1}(j1)
                LM4(b, base + bBase + p * 16 * SB + ks * 32);
                MMA_F16(acc[0][2 * p],     a0, b[0], b[1]);
                MMA_F16(acc[1][2 * p],     a1, b[0], b[1]);
                MMA_F16(acc[0][2 * p + 1], a0, b[2], b[3]);
                MMA_F16(acc[1][2 * p + 1], a1, b[2], b[3]);
            }
        }
    };

    // ---- pipelined mainloop: 4-stage B ring, ONE barrier per iteration ----
    cpB(0, 0); cpB(1, 1); cpB(2, 2);
    ldgA(0); stsA(0); ldgA(1);
    for (int t = 0; t < NKT; t++) {
        if (t + 1 < NKT) { stsA((t + 1) & 3); if (t + 2 < NKT) ldgA(t + 2); }
        CP_WAIT2();                       // B(t) complete (<=2 newer groups pending)
        __syncthreads();                  // all warps' A(t)/B(t) visible; readers of
                                          // stage (t+3)&3 (=B(t-1)) are done
        if (t + 3 < NKT) cpB((t + 3) & 3, t + 3);
        else             CP_COMMIT();     // keep one-group-per-iter accounting
        compute(t & 3);                   // overlaps with in-flight cp.async
    }

    // ---- epilogue: gather + bias + relu + dot(W2) + reduce ----
    {   // stage gather matrix G[128][128] f32 into (reused) SMEM
        int row = tid >> 1, half = tid & 1;
        const float4* src = (const float4*)(W1 + (size_t)tok_ep * HS1) + half * 16;
        float4* dst = (float4*)((float*)smem + row * SG + half * 64);
#pragma unroll
        for (int i = 0; i < 16; i++) dst[i] = src[i];
    }
    float b1v[16], w2v[16];
#pragma unroll
    for (int j = 0; j < 8; j++) {
        int col = wn * 64 + j * 8 + 2 * q4;
        b1v[j * 2] = b1[col];  b1v[j * 2 + 1] = b1[col + 1];
        w2v[j * 2] = W2[col];  w2v[j * 2 + 1] = W2[col + 1];
    }
    __syncthreads();

    float* red = (float*)(smem + OFF_RED);
    const float* G = (const float*)smem;
#pragma unroll
    for (int mt = 0; mt < 2; mt++)
#pragma unroll
        for (int h = 0; h < 2; h++) {
            int row = wm * 32 + mt * 16 + h * 8 + g;
            const float* Gr = G + row * SG + wn * 64;
            float p = 0.f;
#pragma unroll
            for (int j = 0; j < 8; j++) {
                float x0 = acc[mt][j][h * 2 + 0] + Gr[j * 8 + 2 * q4]     + b1v[j * 2];
                float x1 = acc[mt][j][h * 2 + 1] + Gr[j * 8 + 2 * q4 + 1] + b1v[j * 2 + 1];
                p = fmaf(fmaxf(x0, 0.f), w2v[j * 2],     p);
                p = fmaf(fmaxf(x1, 0.f), w2v[j * 2 + 1], p);
            }
            red[row * 9 + wn * 4 + q4] = p;
        }
    __syncthreads();

    if (tid < MT) {
        float s = 0.f;
#pragma unroll
        for (int x = 0; x < 8; x++) s += red[tid * 9 + x];
        out[m0 + tid] = s + b2[0];
    }
}

extern "C" void kernel_launch(void* const* d_in, const int* in_sizes, int n_in,
                              void* d_out, int out_size)
{
    const int*   tkw = (const int*)d_in[0];
    const float* hs0 = (const float*)d_in[1];
    const float* W1  = (const float*)d_in[2];
    const float* b1  = (const float*)d_in[3];
    const float* W2  = (const float*)d_in[4];
    const float* b2  = (const float*)d_in[5];
    float* out = (float*)d_out;

    const int M = in_sizes[1] / HID;   // tokens from hs0 (tk-dtype agnostic)

    cudaFuncSetAttribute(cls_mma_kernel,
                         cudaFuncAttributeMaxDynamicSharedMemorySize, SMEM_BYTES);

    prep_w_kernel<<<NKT, 256>>>(W1, (const unsigned int*)tkw);
    cls_mma_kernel<<<M / MT, 256, SMEM_BYTES>>>(tkw, hs0, W1, b1, W2, b2, out);
}